// round 5
// baseline (speedup 1.0000x reference)
#include <cuda_runtime.h>
#include <cstdint>
#include <cstddef>

// out[n,b,o] = (x @ (W*(noise[n]-1)))[b,o] * rsqrt((x^2 @ W^2)[b,o])
// x: [128,784] f32, W: [784,1024] f32, noise: [500,784,1024] f32 -> out [500*128,1024] f32
#define BB 128
#define KK 784
#define OO 1024
#define NN 500

// ---------------- smem tiling (fp16 packed k-pairs) ----------------
// A: [128 rows][16 u32 (32 k as h2)] stride 20 -> conflict-free frag LDS
// B: [128 o-rows][16 u32]            stride 20 -> conflict-free frag LDS
#define AS_STRIDE 20
#define BS_STRIDE 20
#define AS_SIZE (128 * AS_STRIDE)                 // 2560 u32
#define BS_SIZE (128 * BS_STRIDE)                 // 2560 u32
#define SMEM_U32 (2 * AS_SIZE + 4 * BS_SIZE)      // double buffer, 2 n's
#define SMEM_BYTES (SMEM_U32 * 4)                 // 61440 B

// ---------------- device scratch ----------------
__device__ float g_part[8 * 128 * 1024];
__device__ float g_S[128 * 1024];

// ---------------- helpers ----------------
__device__ __forceinline__ uint32_t pack_h2(float lo, float hi) {
    uint32_t d;
    asm("cvt.rn.f16x2.f32 %0, %1, %2;" : "=r"(d) : "f"(hi), "f"(lo));
    return d;
}

__device__ __forceinline__ void mma16(float* d, const uint32_t* a, uint32_t b0, uint32_t b1) {
    asm volatile(
        "mma.sync.aligned.m16n8k16.row.col.f32.f16.f16.f32 "
        "{%0,%1,%2,%3},{%4,%5,%6,%7},{%8,%9},{%0,%1,%2,%3};"
        : "+f"(d[0]), "+f"(d[1]), "+f"(d[2]), "+f"(d[3])
        : "r"(a[0]), "r"(a[1]), "r"(a[2]), "r"(a[3]), "r"(b0), "r"(b1));
}

// ================= S = rsqrt(x^2 @ W^2), exact fp32 =================
__global__ void s_partial_kernel(const float* __restrict__ x, const float* __restrict__ W) {
    __shared__ float xsq[16][17];
    const int o = blockIdx.x * 256 + threadIdx.x;
    const int b0 = blockIdx.y * 16;
    const int ks = blockIdx.z;
    const int k0 = ks * 98;

    float acc[16];
#pragma unroll
    for (int i = 0; i < 16; i++) acc[i] = 0.f;

    const int bi = threadIdx.x >> 4;
    const int jj = threadIdx.x & 15;

    for (int kk = 0; kk < 98; kk += 16) {
        int jmax = 98 - kk;
        if (jmax > 16) jmax = 16;
        if (jj < jmax) {
            float v = x[(b0 + bi) * KK + k0 + kk + jj];
            xsq[bi][jj] = v * v;
        }
        __syncthreads();
        for (int j = 0; j < jmax; j++) {
            float w = __ldg(W + (size_t)(k0 + kk + j) * OO + o);
            w *= w;
#pragma unroll
            for (int b = 0; b < 16; b++) acc[b] = fmaf(xsq[b][j], w, acc[b]);
        }
        __syncthreads();
    }
#pragma unroll
    for (int b = 0; b < 16; b++)
        g_part[((size_t)ks * 128 + b0 + b) * OO + o] = acc[b];
}

__global__ void s_reduce_kernel() {
    int i = blockIdx.x * 256 + threadIdx.x;
    float s = 0.f;
#pragma unroll
    for (int ks = 0; ks < 8; ks++) s += g_part[(size_t)ks * 131072 + i];
    g_S[i] = 1.0f / sqrtf(s);
}

// ================= main: 500 fp16 GEMMs (m16n8k16, fp32 accum) =================
// Grid (8 o-tiles of 128, 250 n-pairs). 256 threads = 8 warps (2 wm x 4 wn),
// warp tile 64x32, NG=2 iterations accumulated simultaneously.

struct Stage {
    float4 xv[4];
    float  wv[16];       // 4 rounds x 4 k
    float  nv[2][16];
};

__device__ __forceinline__ void ldg_stage(
    const float* __restrict__ x, const float* __restrict__ W,
    const float* __restrict__ noise,
    int kb, int n0, int o0, int tid, Stage& st)
{
    const int lane = tid & 31, wid = tid >> 5;
    const int ob = wid & 3;        // o-block of 32
    const int kb2 = wid >> 2;      // k-block of 16
    const float4 z4 = make_float4(0.f, 0.f, 0.f, 0.f);

#pragma unroll
    for (int r = 0; r < 4; r++) {
        int b = r * 32 + (tid >> 3);
        int k = kb + (tid & 7) * 4;
        st.xv[r] = (k < KK) ? __ldg(reinterpret_cast<const float4*>(x + b * KK + k)) : z4;
    }
    const int o = o0 + ob * 32 + lane;
#pragma unroll
    for (int r = 0; r < 4; r++) {
#pragma unroll
        for (int j = 0; j < 4; j++) {
            int gk = kb + kb2 * 16 + r * 4 + j;
            if (gk < KK) {
                size_t idx = (size_t)gk * OO + o;
                st.wv[r * 4 + j]    = __ldg(W + idx);
                st.nv[0][r * 4 + j] = __ldg(noise + (size_t)n0 * KK * OO + idx);
                st.nv[1][r * 4 + j] = __ldg(noise + (size_t)(n0 + 1) * KK * OO + idx);
            } else {
                st.wv[r * 4 + j] = 0.f;
                st.nv[0][r * 4 + j] = 1.f;   // fma(1, 0, -0) = 0
                st.nv[1][r * 4 + j] = 1.f;
            }
        }
    }
}

__device__ __forceinline__ void sts_stage(
    uint32_t* __restrict__ as, uint32_t* __restrict__ bs0, uint32_t* __restrict__ bs1,
    int tid, const Stage& st)
{
    const int lane = tid & 31, wid = tid >> 5;
    const int ob = wid & 3, kb2 = wid >> 2;

    // A: row b, packed k-pair cols
#pragma unroll
    for (int r = 0; r < 4; r++) {
        int b = r * 32 + (tid >> 3);
        int c = (tid & 7) * 2;
        uint32_t u0 = pack_h2(st.xv[r].x, st.xv[r].y);
        uint32_t u1 = pack_h2(st.xv[r].z, st.xv[r].w);
        *reinterpret_cast<uint2*>(as + b * AS_STRIDE + c) = make_uint2(u0, u1);
    }

    // B: o-major rows, packed k-pairs; v = fma(n, w, -w) = (n-1)*w
    const int orow = ob * 32 + lane;
#pragma unroll
    for (int ng = 0; ng < 2; ng++) {
        uint32_t* bs = ng ? bs1 : bs0;
#pragma unroll
        for (int r = 0; r < 4; r++) {
            float v0 = fmaf(st.nv[ng][r * 4 + 0], st.wv[r * 4 + 0], -st.wv[r * 4 + 0]);
            float v1 = fmaf(st.nv[ng][r * 4 + 1], st.wv[r * 4 + 1], -st.wv[r * 4 + 1]);
            float v2 = fmaf(st.nv[ng][r * 4 + 2], st.wv[r * 4 + 2], -st.wv[r * 4 + 2]);
            float v3 = fmaf(st.nv[ng][r * 4 + 3], st.wv[r * 4 + 3], -st.wv[r * 4 + 3]);
            int cb = kb2 * 8 + r * 2;
            uint32_t u0 = pack_h2(v0, v1);
            uint32_t u1 = pack_h2(v2, v3);
            *reinterpret_cast<uint2*>(bs + orow * BS_STRIDE + cb) = make_uint2(u0, u1);
        }
    }
}

__device__ __forceinline__ void compute_kstep(
    const uint32_t* __restrict__ as,
    const uint32_t* __restrict__ bs0, const uint32_t* __restrict__ bs1,
    int ks, int wm, int wn, int g, int t,
    float acc[2][4][4][4])
{
    const int c0 = ks * 8 + t;
    uint32_t a[4][4];
#pragma unroll
    for (int mt = 0; mt < 4; mt++) {
        const uint32_t* p = as + (wm * 64 + mt * 16 + g) * AS_STRIDE + c0;
        a[mt][0] = p[0];
        a[mt][1] = p[8 * AS_STRIDE];
        a[mt][2] = p[4];
        a[mt][3] = p[8 * AS_STRIDE + 4];
    }
#pragma unroll
    for (int ng = 0; ng < 2; ng++) {
        const uint32_t* bs = ng ? bs1 : bs0;
#pragma unroll
        for (int nt = 0; nt < 4; nt++) {
            const uint32_t* q = bs + (wn * 32 + nt * 8 + g) * BS_STRIDE + c0;
            uint32_t b0 = q[0];
            uint32_t b1 = q[4];
#pragma unroll
            for (int mt = 0; mt < 4; mt++)
                mma16(acc[ng][mt][nt], a[mt], b0, b1);
        }
    }
}

__global__ void __launch_bounds__(256, 1) wn_main_kernel(
    const float* __restrict__ x, const float* __restrict__ W,
    const float* __restrict__ noise, float* __restrict__ out)
{
    extern __shared__ uint32_t sm[];
    const int tid = threadIdx.x;
    const int o0 = blockIdx.x * 128;
    const int n0 = blockIdx.y * 2;
    const int lane = tid & 31, wid = tid >> 5;
    const int g = lane >> 2, t = lane & 3;
    const int wm = wid >> 2, wn = wid & 3;

    uint32_t* asb[2];
    asb[0] = sm;
    asb[1] = sm + AS_SIZE;
    uint32_t* bbase = sm + 2 * AS_SIZE;
    uint32_t* bsb[2][2];
    bsb[0][0] = bbase;
    bsb[0][1] = bbase + BS_SIZE;
    bsb[1][0] = bbase + 2 * BS_SIZE;
    bsb[1][1] = bbase + 3 * BS_SIZE;

    float acc[2][4][4][4];
#pragma unroll
    for (int i = 0; i < 2; i++)
#pragma unroll
        for (int j = 0; j < 4; j++)
#pragma unroll
            for (int k2 = 0; k2 < 4; k2++)
#pragma unroll
                for (int l = 0; l < 4; l++) acc[i][j][k2][l] = 0.f;

    {
        Stage st;
        ldg_stage(x, W, noise, 0, n0, o0, tid, st);
        sts_stage(asb[0], bsb[0][0], bsb[0][1], tid, st);
    }
    __syncthreads();

    for (int kc = 0; kc < 25; kc++) {
        const int cur = kc & 1;
        const int nxt = cur ^ 1;
        const bool pre = (kc + 1) < 25;
        Stage st;
        if (pre) ldg_stage(x, W, noise, (kc + 1) * 32, n0, o0, tid, st);
        compute_kstep(asb[cur], bsb[cur][0], bsb[cur][1], 0, wm, wn, g, t, acc);
        compute_kstep(asb[cur], bsb[cur][0], bsb[cur][1], 1, wm, wn, g, t, acc);
        if (pre) sts_stage(asb[nxt], bsb[nxt][0], bsb[nxt][1], tid, st);
        __syncthreads();
    }

    // epilogue: scale by S, store
#pragma unroll
    for (int mt = 0; mt < 4; mt++) {
        const int row = wm * 64 + mt * 16 + g;
#pragma unroll
        for (int nt = 0; nt < 4; nt++) {
            const int col = o0 + wn * 32 + nt * 8 + 2 * t;
            const float2 s0 = *reinterpret_cast<const float2*>(g_S + row * OO + col);
            const float2 s1 = *reinterpret_cast<const float2*>(g_S + (row + 8) * OO + col);
#pragma unroll
            for (int ng = 0; ng < 2; ng++) {
                const float* a4 = acc[ng][mt][nt];
                float2 v0 = make_float2(a4[0] * s0.x, a4[1] * s0.y);
                float2 v1 = make_float2(a4[2] * s1.x, a4[3] * s1.y);
                size_t base = ((size_t)(n0 + ng) * 128 + row) * OO + col;
                *reinterpret_cast<float2*>(out + base) = v0;
                *reinterpret_cast<float2*>(out + base + 8 * OO) = v1;
            }
        }
    }
}

// ================= launch =================
extern "C" void kernel_launch(void* const* d_in, const int* in_sizes, int n_in,
                              void* d_out, int out_size) {
    const float* x = nullptr;
    const float* W = nullptr;
    const float* noise = nullptr;
    for (int i = 0; i < n_in; i++) {
        if (in_sizes[i] == BB * KK) x = (const float*)d_in[i];
        else if (in_sizes[i] == KK * OO) W = (const float*)d_in[i];
        else if (in_sizes[i] == NN * KK * OO) noise = (const float*)d_in[i];
    }
    float* out = (float*)d_out;

    cudaFuncSetAttribute(wn_main_kernel, cudaFuncAttributeMaxDynamicSharedMemorySize, SMEM_BYTES);

    s_partial_kernel<<<dim3(4, 8, 8), 256>>>(x, W);
    s_reduce_kernel<<<512, 256>>>();
    wn_main_kernel<<<dim3(8, 250), 256, SMEM_BYTES>>>(x, W, noise, out);
}

// round 9
// speedup vs baseline: 1.5235x; 1.5235x over previous
#include <cuda_runtime.h>
#include <cstdint>
#include <cstddef>

// out[n,b,o] = (x @ (W*(noise[n]-1)))[b,o] * rsqrt((x^2 @ W^2)[b,o])
// x:[128,784] W:[784,1024] noise:[500,784,1024] -> out [500*128,1024] f32
#define BB 128
#define KK 784
#define OO 1024
#define NN 500
#define OT 64            // o-tile per CTA
#define KC 32            // k per chunk
#define NCH 25           // ceil(784/32)
#define NG 2             // noise iterations per CTA

#define BS_STRIDE 20     // u32 stride, conflict-free frag LDS + STS.128
#define BS_SIZE (OT * BS_STRIDE)   // 1280 u32

// ---------------- device scratch ----------------
__device__ float g_part[8 * BB * OO];
__device__ float g_S[BB * OO];
// x fragment image: [chunk 25][m16blk 8][kstep 2][lane 32] x uint4 (a0..a3)
__device__ uint4 g_ximg[NCH * 8 * 2 * 32];

// ---------------- helpers ----------------
__device__ __forceinline__ uint32_t pack_h2(float lo, float hi) {
    uint32_t d;
    asm("cvt.rn.f16x2.f32 %0, %1, %2;" : "=r"(d) : "f"(hi), "f"(lo));
    return d;
}
__device__ __forceinline__ void mma16(float* d, const uint32_t* a, uint32_t b0, uint32_t b1) {
    asm volatile(
        "mma.sync.aligned.m16n8k16.row.col.f32.f16.f16.f32 "
        "{%0,%1,%2,%3},{%4,%5,%6,%7},{%8,%9},{%0,%1,%2,%3};"
        : "+f"(d[0]), "+f"(d[1]), "+f"(d[2]), "+f"(d[3])
        : "r"(a[0]), "r"(a[1]), "r"(a[2]), "r"(a[3]), "r"(b0), "r"(b1));
}

// ================= S = rsqrt(x^2 @ W^2), exact fp32 (proven R3/R4) =================
__global__ void s_partial_kernel(const float* __restrict__ x, const float* __restrict__ W) {
    __shared__ float xsq[16][17];
    const int o = blockIdx.x * 256 + threadIdx.x;
    const int b0 = blockIdx.y * 16;
    const int ks = blockIdx.z;
    const int k0 = ks * 98;

    float acc[16];
#pragma unroll
    for (int i = 0; i < 16; i++) acc[i] = 0.f;

    const int bi = threadIdx.x >> 4;
    const int jj = threadIdx.x & 15;

    for (int kk = 0; kk < 98; kk += 16) {
        int jmax = 98 - kk;
        if (jmax > 16) jmax = 16;
        if (jj < jmax) {
            float v = x[(b0 + bi) * KK + k0 + kk + jj];
            xsq[bi][jj] = v * v;
        }
        __syncthreads();
        for (int j = 0; j < jmax; j++) {
            float w = __ldg(W + (size_t)(k0 + kk + j) * OO + o);
            w *= w;
#pragma unroll
            for (int b = 0; b < 16; b++) acc[b] = fmaf(xsq[b][j], w, acc[b]);
        }
        __syncthreads();
    }
#pragma unroll
    for (int b = 0; b < 16; b++)
        g_part[((size_t)ks * 128 + b0 + b) * OO + o] = acc[b];
}

__global__ void s_reduce_kernel() {
    int i = blockIdx.x * 256 + threadIdx.x;
    float s = 0.f;
#pragma unroll
    for (int ks = 0; ks < 8; ks++) s += g_part[(size_t)ks * 131072 + i];
    g_S[i] = 1.0f / sqrtf(s);
}

// ================= x fragment image builder =================
// word layout per (c, mb, ks, lane): g=lane>>2, t=lane&3, row=mb*16+g, k0=c*32+ks*16+t*2
//   a0=(row,k0..k0+1) a1=(row+8,k0..) a2=(row,k0+8..) a3=(row+8,k0+8..)
__global__ void ximg_kernel(const float* __restrict__ x) {
    const int idx = blockIdx.x * 256 + threadIdx.x;   // 12800 total
    const int c = idx >> 9;
    const int rem = idx & 511;
    const int mb = rem >> 6;
    const int ks = (rem >> 5) & 1;
    const int lane = rem & 31;
    const int g = lane >> 2, t = lane & 3;
    const int row = mb * 16 + g;
    const int k0 = c * KC + ks * 16 + t * 2;

#define XEL(r, k) (((k) < KK) ? x[(r) * KK + (k)] : 0.f)
    uint4 u;
    u.x = pack_h2(XEL(row, k0),         XEL(row, k0 + 1));
    u.y = pack_h2(XEL(row + 8, k0),     XEL(row + 8, k0 + 1));
    u.z = pack_h2(XEL(row, k0 + 8),     XEL(row, k0 + 9));
    u.w = pack_h2(XEL(row + 8, k0 + 8), XEL(row + 8, k0 + 9));
#undef XEL
    g_ximg[idx] = u;
}

// ================= main: 500 fp16 GEMMs, CTA tile 128x64, 2 CTAs/SM =================
__device__ __forceinline__ void ldg_wn(
    const float* __restrict__ W, const float* __restrict__ noise,
    int c, int o, int kb8, int nbase,
    float* wv, float* n0v, float* n1v)
{
    const int kb = c * KC + kb8;
#pragma unroll
    for (int j = 0; j < 8; j++) {
        const int gk = kb + j;
        const bool v = gk < KK;
        const size_t idx = (size_t)gk * OO + o;
        wv[j]  = v ? __ldg(W + idx) : 0.f;
        n0v[j] = v ? __ldg(noise + (size_t)nbase * KK * OO + idx) : 1.f;
        n1v[j] = v ? __ldg(noise + (size_t)(nbase + 1) * KK * OO + idx) : 1.f;
    }
}

__device__ __forceinline__ void sts_b(
    uint32_t* __restrict__ b0s, uint32_t* __restrict__ b1s,
    int oc, int kb8,
    const float* wv, const float* n0v, const float* n1v)
{
    const int col = kb8 >> 1;   // kpair base
#pragma unroll
    for (int ng = 0; ng < NG; ng++) {
        const float* nv = ng ? n1v : n0v;
        uint32_t* bs = ng ? b1s : b0s;
        float v[8];
#pragma unroll
        for (int j = 0; j < 8; j++) v[j] = fmaf(nv[j], wv[j], -wv[j]);
        uint4 u;
        u.x = pack_h2(v[0], v[1]); u.y = pack_h2(v[2], v[3]);
        u.z = pack_h2(v[4], v[5]); u.w = pack_h2(v[6], v[7]);
        *reinterpret_cast<uint4*>(bs + oc * BS_STRIDE + col) = u;
    }
}

__device__ __forceinline__ void compute_chunk(
    const uint32_t* __restrict__ b0s, const uint32_t* __restrict__ b1s,
    const uint4* __restrict__ afp,
    int wn, int g, int t, float acc[NG][2][4][4])
{
    uint4 af[2][2];
#pragma unroll
    for (int mt = 0; mt < 2; mt++)
#pragma unroll
        for (int ks = 0; ks < 2; ks++)
            af[mt][ks] = __ldg(afp + mt * 64 + ks * 32);

#pragma unroll
    for (int ks = 0; ks < 2; ks++) {
#pragma unroll
        for (int ng = 0; ng < NG; ng++) {
            const uint32_t* bs = ng ? b1s : b0s;
#pragma unroll
            for (int nt = 0; nt < 4; nt++) {
                const uint32_t* q = bs + (wn * 32 + nt * 8 + g) * BS_STRIDE + ks * 8 + t;
                const uint32_t b0 = q[0];
                const uint32_t b1 = q[4];
#pragma unroll
                for (int mt = 0; mt < 2; mt++)
                    mma16(acc[ng][mt][nt],
                          reinterpret_cast<const uint32_t*>(&af[mt][ks]), b0, b1);
            }
        }
    }
}

__global__ void __launch_bounds__(256, 2) wn_main_kernel(
    const float* __restrict__ W, const float* __restrict__ noise,
    float* __restrict__ out)
{
    __shared__ uint32_t bsm[2][NG][BS_SIZE];   // 20 KB

    const int tid = threadIdx.x;
    const int lane = tid & 31, wid = tid >> 5;
    const int g = lane >> 2, t = lane & 3;
    const int wm = wid >> 1, wn = wid & 1;     // 4x2 warp grid, 32x32 warp tiles
    const int o0 = blockIdx.x * OT;
    const int nbase = blockIdx.y * NG;

    const int oc = tid & 63;                   // owned o column
    const int kb8 = (tid >> 6) * 8;            // owned k sub-block

    float acc[NG][2][4][4];
#pragma unroll
    for (int i = 0; i < NG; i++)
#pragma unroll
        for (int j = 0; j < 2; j++)
#pragma unroll
            for (int k2 = 0; k2 < 4; k2++)
#pragma unroll
                for (int l = 0; l < 4; l++) acc[i][j][k2][l] = 0.f;

    float wv[8], n0v[8], n1v[8];

    // prologue: stage chunk 0 -> buf 0
    ldg_wn(W, noise, 0, o0 + oc, kb8, nbase, wv, n0v, n1v);
    sts_b(bsm[0][0], bsm[0][1], oc, kb8, wv, n0v, n1v);
    __syncthreads();

    for (int c = 0; c < NCH; c++) {
        const int buf = c & 1;
        if (c + 1 < NCH)
            ldg_wn(W, noise, c + 1, o0 + oc, kb8, nbase, wv, n0v, n1v);
        const uint4* afp = g_ximg + (size_t)(c * 8 + wm * 2) * 64 + lane;
        compute_chunk(bsm[buf][0], bsm[buf][1], afp, wn, g, t, acc);
        if (c + 1 < NCH)
            sts_b(bsm[buf ^ 1][0], bsm[buf ^ 1][1], oc, kb8, wv, n0v, n1v);
        __syncthreads();
    }

    // epilogue: scale by S, store
#pragma unroll
    for (int mt = 0; mt < 2; mt++) {
        const int row = wm * 32 + mt * 16 + g;
#pragma unroll
        for (int nt = 0; nt < 4; nt++) {
            const int col = o0 + wn * 32 + nt * 8 + 2 * t;
            const float2 s0 = *reinterpret_cast<const float2*>(g_S + (size_t)row * OO + col);
            const float2 s1 = *reinterpret_cast<const float2*>(g_S + (size_t)(row + 8) * OO + col);
#pragma unroll
            for (int ng = 0; ng < NG; ng++) {
                const float* a4 = acc[ng][mt][nt];
                const size_t base = ((size_t)(nbase + ng) * BB + row) * OO + col;
                *reinterpret_cast<float2*>(out + base) =
                    make_float2(a4[0] * s0.x, a4[1] * s0.y);
                *reinterpret_cast<float2*>(out + base + 8 * OO) =
                    make_float2(a4[2] * s1.x, a4[3] * s1.y);
            }
        }
    }
}

// ================= launch =================
extern "C" void kernel_launch(void* const* d_in, const int* in_sizes, int n_in,
                              void* d_out, int out_size) {
    const float* x = nullptr;
    const float* W = nullptr;
    const float* noise = nullptr;
    for (int i = 0; i < n_in; i++) {
        if (in_sizes[i] == BB * KK) x = (const float*)d_in[i];
        else if (in_sizes[i] == KK * OO) W = (const float*)d_in[i];
        else if (in_sizes[i] == NN * KK * OO) noise = (const float*)d_in[i];
    }
    float* out = (float*)d_out;

    s_partial_kernel<<<dim3(4, 8, 8), 256>>>(x, W);
    s_reduce_kernel<<<512, 256>>>();
    ximg_kernel<<<50, 256>>>(x);
    wn_main_kernel<<<dim3(OO / OT, NN / NG), 256>>>(W, noise, out);
}